// round 14
// baseline (speedup 1.0000x reference)
#include <cuda_runtime.h>
#include <cuda_bf16.h>
#include <cstdint>

// CausalAttention on GB300 (sm_103 base target): bf16x3 split-precision
// pipeline on mma.sync tensor cores (HMMA).
// R14: R13 + single-barrier k-iter (fill before compute; stage written is the
// one consumed last iter, so one __syncthreads per iter suffices).

#define CTX    2048
#define BATCH  4
#define DM     1024

typedef __nv_bfloat16 bf16;

#define NTOK   ((size_t)BATCH * CTX)          // 8192
#define XSZ    ((size_t)BATCH * CTX * DM)     // 8388608
#define SSZ    ((size_t)BATCH * CTX * CTX)    // 16777216
#define WSZ    ((size_t)DM * DM)              // 1048576

// ---------------- device scratch (allocation-free) ----------------
__device__ bf16  g_xh[XSZ],  g_xl[XSZ];
__device__ bf16  g_wth[3 * WSZ], g_wtl[3 * WSZ];    // W^T hi/lo (Q,K,V contiguous)
__device__ bf16  g_qh[XSZ],  g_ql[XSZ];
__device__ bf16  g_kh[XSZ],  g_kl[XSZ];
__device__ float g_vf[XSZ];                          // V fp32 scratch
__device__ bf16  g_vth[XSZ], g_vtl[XSZ];             // V^T hi/lo  [b][e][t]
__device__ float g_s[SSZ];                           // scores fp32
__device__ bf16  g_sh[SSZ],  g_sl[SSZ];              // softmax probs hi/lo

// ---------------- helpers ----------------
__device__ __forceinline__ uint32_t smem_u32(const void* p) {
    uint32_t a;
    asm("{ .reg .u64 t; cvta.to.shared.u64 t, %1; cvt.u32.u64 %0, t; }" : "=r"(a) : "l"(p));
    return a;
}
__device__ __forceinline__ void cp16(uint32_t dst, const void* src) {
    asm volatile("cp.async.cg.shared.global [%0], [%1], 16;" :: "r"(dst), "l"(src));
}
#define CP_COMMIT() asm volatile("cp.async.commit_group;" ::: "memory")
#define CP_WAIT(n)  asm volatile("cp.async.wait_group %0;" :: "n"(n) : "memory")

__device__ __forceinline__ void ldm_x4(uint32_t* r, uint32_t addr) {
    asm volatile("ldmatrix.sync.aligned.m8n8.x4.shared.b16 {%0,%1,%2,%3}, [%4];"
                 : "=r"(r[0]), "=r"(r[1]), "=r"(r[2]), "=r"(r[3]) : "r"(addr));
}
__device__ __forceinline__ void ldm_x2(uint32_t* r, uint32_t addr) {
    asm volatile("ldmatrix.sync.aligned.m8n8.x2.shared.b16 {%0,%1}, [%2];"
                 : "=r"(r[0]), "=r"(r[1]) : "r"(addr));
}
__device__ __forceinline__ void mma16816(float* c, const uint32_t* a, const uint32_t* b) {
    asm volatile(
        "mma.sync.aligned.m16n8k16.row.col.f32.bf16.bf16.f32 "
        "{%0,%1,%2,%3}, {%4,%5,%6,%7}, {%8,%9}, {%0,%1,%2,%3};"
        : "+f"(c[0]), "+f"(c[1]), "+f"(c[2]), "+f"(c[3])
        : "r"(a[0]), "r"(a[1]), "r"(a[2]), "r"(a[3]), "r"(b[0]), "r"(b[1]));
}

// ---------------- GEMM: C[M,N] = A[M,K] * B[N,K]^T, bf16x3 split ----------------
// 128x128 block tile, BK=16, 256 threads (8 warps 2x4, warp tile 64x32),
// 4-stage cp.async pipeline, single barrier per iter, 2 CTAs/SM.
// Smem rows: 32B, chunk-XOR swizzle (chunk' = chunk ^ bit2(row)).
#define BK        16
#define ROWB      32                        // bytes per smem row (16 bf16)
#define MATB      (128 * ROWB)              // 4096 B per matrix per stage
#define STAGE_B   (4 * MATB)                // 16384 B: Ah, Al, Bh, Bl
#define NSTAGES   4
#define GEMM_SMEM (NSTAGES * STAGE_B)       // 65536 B

__device__ __forceinline__ void fill_stage(
    uint32_t st,
    const bf16* __restrict__ Ah, const bf16* __restrict__ Al,
    const bf16* __restrict__ Bh, const bf16* __restrict__ Bl,
    int row0, int col0, int K, int k0, int tid)
{
    const int r = tid >> 1, j = tid & 1;            // 128 rows x 2 16B-chunks
    const int js = j ^ ((r >> 2) & 1);              // XOR swizzle
    const uint32_t off = (uint32_t)(r * ROWB + js * 16);
    const size_t ga = (size_t)(row0 + r) * K + k0 + j * 8;
    const size_t gb = (size_t)(col0 + r) * K + k0 + j * 8;
    cp16(st + off,            Ah + ga);
    cp16(st + MATB + off,     Al + ga);
    cp16(st + 2 * MATB + off, Bh + gb);
    cp16(st + 3 * MATB + off, Bl + gb);
}

// MODE 0: fp32 C (stride N).  MODE 2: fused QKV epilogue
//   (region by col0>>10: 0 -> Ch/Cl, 1 -> Ch2/Cl2, 2 -> C fp32; out stride DM).
// SKIP: compact triangular grid — blockIdx.x is a linear lower-triangle tile id.
template <int MODE, bool SKIP, bool CK>
__global__ __launch_bounds__(256, 2)
void gemm_bf16x3(const bf16* __restrict__ Ah, const bf16* __restrict__ Al,
                 const bf16* __restrict__ Bh, const bf16* __restrict__ Bl,
                 float* __restrict__ C, bf16* __restrict__ Ch, bf16* __restrict__ Cl,
                 bf16* __restrict__ Ch2, bf16* __restrict__ Cl2,
                 int M, int N, int K, size_t sA, size_t sB, size_t sC)
{
    int row0, col0;
    if (SKIP) {
        // triangular decode: t -> (rt, ct), ct <= rt
        const int t = blockIdx.x;
        int rt = (int)((sqrtf(8.0f * (float)t + 1.0f) - 1.0f) * 0.5f);
        while ((rt + 1) * (rt + 2) / 2 <= t) rt++;
        while (rt * (rt + 1) / 2 > t) rt--;
        const int ct = t - rt * (rt + 1) / 2;
        row0 = rt * 128;
        col0 = ct * 128;
    } else {
        const int by = CK ? (gridDim.y - 1 - blockIdx.y) : blockIdx.y;  // long tiles first
        row0 = by * 128;
        col0 = blockIdx.x * 128;
    }

    Ah += (size_t)blockIdx.z * sA;  Al += (size_t)blockIdx.z * sA;
    Bh += (size_t)blockIdx.z * sB;  Bl += (size_t)blockIdx.z * sB;

    const int kmax  = CK ? (row0 + 128) : K;      // PV: keys beyond query row are zero
    const int niter = kmax / BK;                  // >= 8 for all launches here

    extern __shared__ char dsm[];
    const uint32_t sb = smem_u32(dsm);
    const int tid  = threadIdx.x;
    const int lane = tid & 31;
    const int wid  = tid >> 5;
    const int wm   = (wid & 1) * 64;              // warp row offset in tile
    const int wn   = (wid >> 1) * 32;             // warp col offset in tile

    // ldmatrix lane addresses with per-thread-constant XOR swizzle.
    const uint32_t a_swz = (uint32_t)((lane >> 4) ^ ((lane >> 2) & 1));
    const uint32_t a_off = (uint32_t)((wm + (lane & 15)) * ROWB) + a_swz * 16;
    const uint32_t b_swz = (uint32_t)(((lane >> 3) & 1) ^ ((lane >> 2) & 1));
    const uint32_t b_off = (uint32_t)((wn + (lane & 7)) * ROWB) + b_swz * 16;

    float acc[4][4][4];
#pragma unroll
    for (int i = 0; i < 4; i++)
#pragma unroll
        for (int j = 0; j < 4; j++)
#pragma unroll
            for (int q = 0; q < 4; q++) acc[i][j][q] = 0.0f;

    // prologue: prefetch 3 stages
    fill_stage(sb,               Ah, Al, Bh, Bl, row0, col0, K, 0,      tid); CP_COMMIT();
    fill_stage(sb + STAGE_B,     Ah, Al, Bh, Bl, row0, col0, K, BK,     tid); CP_COMMIT();
    fill_stage(sb + 2 * STAGE_B, Ah, Al, Bh, Bl, row0, col0, K, 2 * BK, tid); CP_COMMIT();

    for (int it = 0; it < niter; it++) {
        CP_WAIT(2);
        __syncthreads();            // single barrier: stage (it+3)%4 was consumed
                                    // at iter it-1, whose reads finished before this.
        if (it + 3 < niter) {
            fill_stage(sb + (uint32_t)((it + 3) & (NSTAGES - 1)) * STAGE_B,
                       Ah, Al, Bh, Bl, row0, col0, K, (it + 3) * BK, tid);
        }
        CP_COMMIT();

        const uint32_t st = sb + (uint32_t)(it & (NSTAGES - 1)) * STAGE_B;
        uint32_t fAh[4][4], fAl[4][4];
#pragma unroll
        for (int i = 0; i < 4; i++) {
            const uint32_t ra = st + a_off + (uint32_t)(i * 16 * ROWB);
            ldm_x4(fAh[i], ra);
            ldm_x4(fAl[i], ra + MATB);
        }
#pragma unroll
        for (int j = 0; j < 4; j++) {
            const uint32_t rb = st + 2 * MATB + b_off + (uint32_t)(j * 8 * ROWB);
            uint32_t fBh[2], fBl[2];
            ldm_x2(fBh, rb);
            ldm_x2(fBl, rb + MATB);
            // product-major: same-acc reuse distance = 4 MMAs (~32 cyc)
#pragma unroll
            for (int i = 0; i < 4; i++) mma16816(acc[i][j], fAh[i], fBh);
#pragma unroll
            for (int i = 0; i < 4; i++) mma16816(acc[i][j], fAh[i], fBl);
#pragma unroll
            for (int i = 0; i < 4; i++) mma16816(acc[i][j], fAl[i], fBh);
        }
    }

    // epilogue
    const int rbase = row0 + wm + (lane >> 2);
    const int cloc  = wn + (lane & 3) * 2;
#pragma unroll
    for (int i = 0; i < 4; i++)
#pragma unroll
        for (int j = 0; j < 4; j++) {
            const int gr = rbase + i * 16;
            if (MODE == 0) {
                const int gc = col0 + cloc + j * 8;
                float2* d0 = (float2*)(C + (size_t)blockIdx.z * sC + (size_t)gr * N + gc);
                float2* d1 = (float2*)(C + (size_t)blockIdx.z * sC + (size_t)(gr + 8) * N + gc);
                *d0 = make_float2(acc[i][j][0], acc[i][j][1]);
                *d1 = make_float2(acc[i][j][2], acc[i][j][3]);
            } else {
                const int region = col0 >> 10;                  // 0=Q, 1=K, 2=V
                const int lc = (col0 & 1023) + cloc + j * 8;    // col within [0,1024)
                if (region == 2) {
                    float2* d0 = (float2*)(C + (size_t)gr * DM + lc);
                    float2* d1 = (float2*)(C + (size_t)(gr + 8) * DM + lc);
                    *d0 = make_float2(acc[i][j][0], acc[i][j][1]);
                    *d1 = make_float2(acc[i][j][2], acc[i][j][3]);
                } else {
                    bf16* oh = region ? Ch2 : Ch;
                    bf16* ol = region ? Cl2 : Cl;
#pragma unroll
                    for (int h = 0; h < 2; h++) {
                        const float v0 = acc[i][j][2 * h];
                        const float v1 = acc[i][j][2 * h + 1];
                        __nv_bfloat162 hi = __floats2bfloat162_rn(v0, v1);
                        __nv_bfloat162 lo = __floats2bfloat162_rn(v0 - __bfloat162float(hi.x),
                                                                  v1 - __bfloat162float(hi.y));
                        const size_t o = (size_t)(gr + 8 * h) * DM + lc;
                        *(__nv_bfloat162*)(oh + o) = hi;
                        *(__nv_bfloat162*)(ol + o) = lo;
                    }
                }
            }
        }
}

// ---------------- elementwise split: fp32 -> (hi, lo) bf16 ----------------
__global__ __launch_bounds__(256)
void split_x(const float4* __restrict__ in, __nv_bfloat162* __restrict__ oh,
             __nv_bfloat162* __restrict__ ol)
{
    size_t i = (size_t)blockIdx.x * 256 + threadIdx.x;
    float4 v = in[i];
    __nv_bfloat162 h0 = __floats2bfloat162_rn(v.x, v.y);
    __nv_bfloat162 h1 = __floats2bfloat162_rn(v.z, v.w);
    __nv_bfloat162 l0 = __floats2bfloat162_rn(v.x - __bfloat162float(h0.x),
                                              v.y - __bfloat162float(h0.y));
    __nv_bfloat162 l1 = __floats2bfloat162_rn(v.z - __bfloat162float(h1.x),
                                              v.w - __bfloat162float(h1.y));
    oh[2 * i] = h0; oh[2 * i + 1] = h1;
    ol[2 * i] = l0; ol[2 * i + 1] = l1;
}

// ---------------- transpose + split: out[c][r] = in[r][c] ----------------
__global__ __launch_bounds__(256)
void transpose_split(const float* __restrict__ in, bf16* __restrict__ oh,
                     bf16* __restrict__ ol, int R, int C, size_t sI, size_t sO)
{
    __shared__ float t[32][33];
    in += (size_t)blockIdx.z * sI;
    oh += (size_t)blockIdx.z * sO;
    ol += (size_t)blockIdx.z * sO;
    const int r0 = blockIdx.y * 32, c0 = blockIdx.x * 32;
    const int tx = threadIdx.x & 31, ty = threadIdx.x >> 5;
#pragma unroll
    for (int d = 0; d < 32; d += 8)
        t[ty + d][tx] = in[(size_t)(r0 + ty + d) * C + c0 + tx];
    __syncthreads();
#pragma unroll
    for (int d = 0; d < 32; d += 8) {
        float v = t[tx][ty + d];
        bf16 h = __float2bfloat16(v);
        bf16 l = __float2bfloat16(v - __bfloat162float(h));
        size_t o = (size_t)(c0 + ty + d) * R + r0 + tx;
        oh[o] = h; ol[o] = l;
    }
}

// ---------------- causal softmax: fp32 scores -> hi/lo bf16 probs ----------------
// Warp-shuffle reductions: 2 barriers per block.
__global__ __launch_bounds__(256)
void softmax_split(const float* __restrict__ S, bf16* __restrict__ Sh, bf16* __restrict__ Sl)
{
    const int row = blockIdx.x, b = blockIdx.y;
    const size_t base = ((size_t)b * CTX + row) * CTX;
    const float* s = S + base;
    bf16* oh = Sh + base;
    bf16* ol = Sl + base;
    const int len = row + 1;
    const int rowEnd = ((row >> 7) + 1) << 7;    // PV never reads past this
    const int tid  = threadIdx.x;
    const int lane = tid & 31;
    const int wrp  = tid >> 5;

    __shared__ float buf[CTX];
    __shared__ float wred[8];
    const float scale = 0.03125f;   // 1/sqrt(1024)

    float lmax = -3.4e38f;
    for (int j = tid; j < len; j += 256) {
        float v = s[j] * scale;
        buf[j] = v;
        lmax = fmaxf(lmax, v);
    }
#pragma unroll
    for (int off = 16; off > 0; off >>= 1)
        lmax = fmaxf(lmax, __shfl_xor_sync(0xffffffffu, lmax, off));
    if (lane == 0) wred[wrp] = lmax;
    __syncthreads();
    float m = wred[0];
#pragma unroll
    for (int k = 1; k < 8; k++) m = fmaxf(m, wred[k]);

    float lsum = 0.0f;
    for (int j = tid; j < len; j += 256) {
        float e = __expf(buf[j] - m);
        buf[j] = e;
        lsum += e;
    }
#pragma unroll
    for (int off = 16; off > 0; off >>= 1)
        lsum += __shfl_xor_sync(0xffffffffu, lsum, off);
    __syncthreads();                 // wred reuse: all reads of round-1 done
    if (lane == 0) wred[wrp] = lsum;
    __syncthreads();
    float tot = wred[0];
#pragma unroll
    for (int k = 1; k < 8; k++) tot += wred[k];
    const float inv = 1.0f / tot;

    const bf16 z = __ushort_as_bfloat16(0);
    for (int j = tid; j < len; j += 256) {
        float p = buf[j] * inv;
        bf16 h = __float2bfloat16(p);
        oh[j] = h;
        ol[j] = __float2bfloat16(p - __bfloat162float(h));
    }
    for (int j = len + tid; j < rowEnd; j += 256) { oh[j] = z; ol[j] = z; }
}

// ---------------- launch ----------------
extern "C" void kernel_launch(void* const* d_in, const int* in_sizes, int n_in,
                              void* d_out, int out_size)
{
    const float* x  = (const float*)d_in[0];
    const float* Wq = (const float*)d_in[1];
    const float* Wk = (const float*)d_in[2];
    const float* Wv = (const float*)d_in[3];
    float* out = (float*)d_out;

    bf16 *xh, *xl, *wth, *wtl, *qh, *ql, *kh, *kl, *vth, *vtl, *sh, *sl;
    float *vf, *s;
    cudaGetSymbolAddress((void**)&xh, g_xh);   cudaGetSymbolAddress((void**)&xl, g_xl);
    cudaGetSymbolAddress((void**)&wth, g_wth); cudaGetSymbolAddress((void**)&wtl, g_wtl);
    cudaGetSymbolAddress((void**)&qh, g_qh);   cudaGetSymbolAddress((void**)&ql, g_ql);
    cudaGetSymbolAddress((void**)&kh, g_kh);   cudaGetSymbolAddress((void**)&kl, g_kl);
    cudaGetSymbolAddress((void**)&vf, g_vf);
    cudaGetSymbolAddress((void**)&vth, g_vth); cudaGetSymbolAddress((void**)&vtl, g_vtl);
    cudaGetSymbolAddress((void**)&s, g_s);
    cudaGetSymbolAddress((void**)&sh, g_sh);   cudaGetSymbolAddress((void**)&sl, g_sl);

    cudaFuncSetAttribute(gemm_bf16x3<2, false, false>,
                         cudaFuncAttributeMaxDynamicSharedMemorySize, GEMM_SMEM);
    cudaFuncSetAttribute(gemm_bf16x3<0, true, false>,
                         cudaFuncAttributeMaxDynamicSharedMemorySize, GEMM_SMEM);
    cudaFuncSetAttribute(gemm_bf16x3<0, false, true>,
                         cudaFuncAttributeMaxDynamicSharedMemorySize, GEMM_SMEM);

    // 1) split x into hi/lo bf16
    split_x<<<(unsigned)(XSZ / 4 / 256), 256>>>((const float4*)x,
                                                (__nv_bfloat162*)xh, (__nv_bfloat162*)xl);

    // 2) transpose + split weights: W[k][n] -> Wt[n][k] (Q,K,V contiguous)
    transpose_split<<<dim3(32, 32, 1), 256>>>(Wq, wth, wtl, DM, DM, 0, 0);
    transpose_split<<<dim3(32, 32, 1), 256>>>(Wk, wth + WSZ, wtl + WSZ, DM, DM, 0, 0);
    transpose_split<<<dim3(32, 32, 1), 256>>>(Wv, wth + 2 * WSZ, wtl + 2 * WSZ, DM, DM, 0, 0);

    // 3) fused QKV projection: [8192,3072] = x @ [Wq|Wk|Wv]^T
    gemm_bf16x3<2, false, false><<<dim3(24, 64, 1), 256, GEMM_SMEM>>>(
        xh, xl, wth, wtl, vf, qh, ql, kh, kl, (int)NTOK, 3 * DM, DM, 0, 0, 0);

    // 4) V^T per batch: [t][e] -> [e][t], split
    transpose_split<<<dim3(DM / 32, CTX / 32, BATCH), 256>>>(
        vf, vth, vtl, CTX, DM, (size_t)CTX * DM, (size_t)DM * CTX);

    // 5) scores = Q @ K^T — compact triangular grid (136 live tiles/batch)
    gemm_bf16x3<0, true, false><<<dim3(136, 1, BATCH), 256, GEMM_SMEM>>>(
        qh, ql, kh, kl, s, nullptr, nullptr, nullptr, nullptr, CTX, CTX, DM,
        (size_t)CTX * DM, (size_t)CTX * DM, (size_t)CTX * CTX);

    // 6) causal softmax -> hi/lo split probabilities (zeros only to 128-aligned end)
    softmax_split<<<dim3(CTX, BATCH), 256>>>(s, sh, sl);

    // 7) out = P @ V (causal K truncation, longest tiles first), per batch
    gemm_bf16x3<0, false, true><<<dim3(DM / 128, CTX / 128, BATCH), 256, GEMM_SMEM>>>(
        sh, sl, vth, vtl, out, nullptr, nullptr, nullptr, nullptr, CTX, DM, CTX,
        (size_t)CTX * CTX, (size_t)DM * CTX, (size_t)CTX * DM);
}

// round 16
// speedup vs baseline: 1.0493x; 1.0493x over previous
#include <cuda_runtime.h>
#include <cuda_bf16.h>
#include <cstdint>

// CausalAttention on GB300 (sm_103 base target): bf16x3 split-precision
// pipeline on mma.sync tensor cores (HMMA).
// R15: exact R13 (best known, 799us) + merged single-launch W transposes.

#define CTX    2048
#define BATCH  4
#define DM     1024

typedef __nv_bfloat16 bf16;

#define NTOK   ((size_t)BATCH * CTX)          // 8192
#define XSZ    ((size_t)BATCH * CTX * DM)     // 8388608
#define SSZ    ((size_t)BATCH * CTX * CTX)    // 16777216
#define WSZ    ((size_t)DM * DM)              // 1048576

// ---------------- device scratch (allocation-free) ----------------
__device__ bf16  g_xh[XSZ],  g_xl[XSZ];
__device__ bf16  g_wth[3 * WSZ], g_wtl[3 * WSZ];    // W^T hi/lo (Q,K,V contiguous)
__device__ bf16  g_qh[XSZ],  g_ql[XSZ];
__device__ bf16  g_kh[XSZ],  g_kl[XSZ];
__device__ float g_vf[XSZ];                          // V fp32 scratch
__device__ bf16  g_vth[XSZ], g_vtl[XSZ];             // V^T hi/lo  [b][e][t]
__device__ float g_s[SSZ];                           // scores fp32
__device__ bf16  g_sh[SSZ],  g_sl[SSZ];              // softmax probs hi/lo

// ---------------- helpers ----------------
__device__ __forceinline__ uint32_t smem_u32(const void* p) {
    uint32_t a;
    asm("{ .reg .u64 t; cvta.to.shared.u64 t, %1; cvt.u32.u64 %0, t; }" : "=r"(a) : "l"(p));
    return a;
}
__device__ __forceinline__ void cp16(uint32_t dst, const void* src) {
    asm volatile("cp.async.cg.shared.global [%0], [%1], 16;" :: "r"(dst), "l"(src));
}
#define CP_COMMIT() asm volatile("cp.async.commit_group;" ::: "memory")
#define CP_WAIT(n)  asm volatile("cp.async.wait_group %0;" :: "n"(n) : "memory")

__device__ __forceinline__ void ldm_x4(uint32_t* r, uint32_t addr) {
    asm volatile("ldmatrix.sync.aligned.m8n8.x4.shared.b16 {%0,%1,%2,%3}, [%4];"
                 : "=r"(r[0]), "=r"(r[1]), "=r"(r[2]), "=r"(r[3]) : "r"(addr));
}
__device__ __forceinline__ void ldm_x2(uint32_t* r, uint32_t addr) {
    asm volatile("ldmatrix.sync.aligned.m8n8.x2.shared.b16 {%0,%1}, [%2];"
                 : "=r"(r[0]), "=r"(r[1]) : "r"(addr));
}
__device__ __forceinline__ void mma16816(float* c, const uint32_t* a, const uint32_t* b) {
    asm volatile(
        "mma.sync.aligned.m16n8k16.row.col.f32.bf16.bf16.f32 "
        "{%0,%1,%2,%3}, {%4,%5,%6,%7}, {%8,%9}, {%0,%1,%2,%3};"
        : "+f"(c[0]), "+f"(c[1]), "+f"(c[2]), "+f"(c[3])
        : "r"(a[0]), "r"(a[1]), "r"(a[2]), "r"(a[3]), "r"(b[0]), "r"(b[1]));
}

// ---------------- GEMM: C[M,N] = A[M,K] * B[N,K]^T, bf16x3 split ----------------
// 128x128 block tile, BK=16, 256 threads (8 warps 2x4, warp tile 64x32),
// 4-stage cp.async pipeline, 2 barriers per iter, 2 CTAs/SM.
// Smem rows: 32B, chunk-XOR swizzle (chunk' = chunk ^ bit2(row)).
#define BK        16
#define ROWB      32                        // bytes per smem row (16 bf16)
#define MATB      (128 * ROWB)              // 4096 B per matrix per stage
#define STAGE_B   (4 * MATB)                // 16384 B: Ah, Al, Bh, Bl
#define NSTAGES   4
#define GEMM_SMEM (NSTAGES * STAGE_B)       // 65536 B

__device__ __forceinline__ void fill_stage(
    uint32_t st,
    const bf16* __restrict__ Ah, const bf16* __restrict__ Al,
    const bf16* __restrict__ Bh, const bf16* __restrict__ Bl,
    int row0, int col0, int K, int k0, int tid)
{
    const int r = tid >> 1, j = tid & 1;            // 128 rows x 2 16B-chunks
    const int js = j ^ ((r >> 2) & 1);              // XOR swizzle
    const uint32_t off = (uint32_t)(r * ROWB + js * 16);
    const size_t ga = (size_t)(row0 + r) * K + k0 + j * 8;
    const size_t gb = (size_t)(col0 + r) * K + k0 + j * 8;
    cp16(st + off,            Ah + ga);
    cp16(st + MATB + off,     Al + ga);
    cp16(st + 2 * MATB + off, Bh + gb);
    cp16(st + 3 * MATB + off, Bl + gb);
}

// MODE 0: fp32 C (stride N).  MODE 2: fused QKV epilogue
//   (region by col0>>10: 0 -> Ch/Cl, 1 -> Ch2/Cl2, 2 -> C fp32; out stride DM).
// SKIP: compact triangular grid — blockIdx.x is a linear lower-triangle tile id.
template <int MODE, bool SKIP, bool CK>
__global__ __launch_bounds__(256, 2)
void gemm_bf16x3(const bf16* __restrict__ Ah, const bf16* __restrict__ Al,
                 const bf16* __restrict__ Bh, const bf16* __restrict__ Bl,
                 float* __restrict__ C, bf16* __restrict__ Ch, bf16* __restrict__ Cl,
                 bf16* __restrict__ Ch2, bf16* __restrict__ Cl2,
                 int M, int N, int K, size_t sA, size_t sB, size_t sC)
{
    int row0, col0;
    if (SKIP) {
        // triangular decode: t -> (rt, ct), ct <= rt
        const int t = blockIdx.x;
        int rt = (int)((sqrtf(8.0f * (float)t + 1.0f) - 1.0f) * 0.5f);
        while ((rt + 1) * (rt + 2) / 2 <= t) rt++;
        while (rt * (rt + 1) / 2 > t) rt--;
        const int ct = t - rt * (rt + 1) / 2;
        row0 = rt * 128;
        col0 = ct * 128;
    } else {
        const int by = CK ? (gridDim.y - 1 - blockIdx.y) : blockIdx.y;  // long tiles first
        row0 = by * 128;
        col0 = blockIdx.x * 128;
    }

    Ah += (size_t)blockIdx.z * sA;  Al += (size_t)blockIdx.z * sA;
    Bh += (size_t)blockIdx.z * sB;  Bl += (size_t)blockIdx.z * sB;

    const int kmax  = CK ? (row0 + 128) : K;      // PV: keys beyond query row are zero
    const int niter = kmax / BK;                  // >= 8 for all launches here

    extern __shared__ char dsm[];
    const uint32_t sb = smem_u32(dsm);
    const int tid  = threadIdx.x;
    const int lane = tid & 31;
    const int wid  = tid >> 5;
    const int wm   = (wid & 1) * 64;              // warp row offset in tile
    const int wn   = (wid >> 1) * 32;             // warp col offset in tile

    // ldmatrix lane addresses with per-thread-constant XOR swizzle.
    const uint32_t a_swz = (uint32_t)((lane >> 4) ^ ((lane >> 2) & 1));
    const uint32_t a_off = (uint32_t)((wm + (lane & 15)) * ROWB) + a_swz * 16;
    const uint32_t b_swz = (uint32_t)(((lane >> 3) & 1) ^ ((lane >> 2) & 1));
    const uint32_t b_off = (uint32_t)((wn + (lane & 7)) * ROWB) + b_swz * 16;

    float acc[4][4][4];
#pragma unroll
    for (int i = 0; i < 4; i++)
#pragma unroll
        for (int j = 0; j < 4; j++)
#pragma unroll
            for (int q = 0; q < 4; q++) acc[i][j][q] = 0.0f;

    // prologue: prefetch 3 stages
    fill_stage(sb,               Ah, Al, Bh, Bl, row0, col0, K, 0,      tid); CP_COMMIT();
    fill_stage(sb + STAGE_B,     Ah, Al, Bh, Bl, row0, col0, K, BK,     tid); CP_COMMIT();
    fill_stage(sb + 2 * STAGE_B, Ah, Al, Bh, Bl, row0, col0, K, 2 * BK, tid); CP_COMMIT();

    for (int it = 0; it < niter; it++) {
        CP_WAIT(2);
        __syncthreads();

        const uint32_t st = sb + (uint32_t)(it & (NSTAGES - 1)) * STAGE_B;
        uint32_t fAh[4][4], fAl[4][4];
#pragma unroll
        for (int i = 0; i < 4; i++) {
            const uint32_t ra = st + a_off + (uint32_t)(i * 16 * ROWB);
            ldm_x4(fAh[i], ra);
            ldm_x4(fAl[i], ra + MATB);
        }
#pragma unroll
        for (int j = 0; j < 4; j++) {
            const uint32_t rb = st + 2 * MATB + b_off + (uint32_t)(j * 8 * ROWB);
            uint32_t fBh[2], fBl[2];
            ldm_x2(fBh, rb);
            ldm_x2(fBl, rb + MATB);
            // product-major: same-acc reuse distance = 4 MMAs (~32 cyc)
#pragma unroll
            for (int i = 0; i < 4; i++) mma16816(acc[i][j], fAh[i], fBh);
#pragma unroll
            for (int i = 0; i < 4; i++) mma16816(acc[i][j], fAh[i], fBl);
#pragma unroll
            for (int i = 0; i < 4; i++) mma16816(acc[i][j], fAl[i], fBh);
        }
        __syncthreads();
        if (it + 3 < niter) {
            fill_stage(sb + (uint32_t)((it + 3) & (NSTAGES - 1)) * STAGE_B,
                       Ah, Al, Bh, Bl, row0, col0, K, (it + 3) * BK, tid);
        }
        CP_COMMIT();
    }

    // epilogue
    const int rbase = row0 + wm + (lane >> 2);
    const int cloc  = wn + (lane & 3) * 2;
#pragma unroll
    for (int i = 0; i < 4; i++)
#pragma unroll
        for (int j = 0; j < 4; j++) {
            const int gr = rbase + i * 16;
            if (MODE == 0) {
                const int gc = col0 + cloc + j * 8;
                float2* d0 = (float2*)(C + (size_t)blockIdx.z * sC + (size_t)gr * N + gc);
                float2* d1 = (float2*)(C + (size_t)blockIdx.z * sC + (size_t)(gr + 8) * N + gc);
                *d0 = make_float2(acc[i][j][0], acc[i][j][1]);
                *d1 = make_float2(acc[i][j][2], acc[i][j][3]);
            } else {
                const int region = col0 >> 10;                  // 0=Q, 1=K, 2=V
                const int lc = (col0 & 1023) + cloc + j * 8;    // col within [0,1024)
                if (region == 2) {
                    float2* d0 = (float2*)(C + (size_t)gr * DM + lc);
                    float2* d1 = (float2*)(C + (size_t)(gr + 8) * DM + lc);
                    *d0 = make_float2(acc[i][j][0], acc[i][j][1]);
                    *d1 = make_float2(acc[i][j][2], acc[i][j][3]);
                } else {
                    bf16* oh = region ? Ch2 : Ch;
                    bf16* ol = region ? Cl2 : Cl;
#pragma unroll
                    for (int h = 0; h < 2; h++) {
                        const float v0 = acc[i][j][2 * h];
                        const float v1 = acc[i][j][2 * h + 1];
                        __nv_bfloat162 hi = __floats2bfloat162_rn(v0, v1);
                        __nv_bfloat162 lo = __floats2bfloat162_rn(v0 - __bfloat162float(hi.x),
                                                                  v1 - __bfloat162float(hi.y));
                        const size_t o = (size_t)(gr + 8 * h) * DM + lc;
                        *(__nv_bfloat162*)(oh + o) = hi;
                        *(__nv_bfloat162*)(ol + o) = lo;
                    }
                }
            }
        }
}

// ---------------- elementwise split: fp32 -> (hi, lo) bf16 ----------------
__global__ __launch_bounds__(256)
void split_x(const float4* __restrict__ in, __nv_bfloat162* __restrict__ oh,
             __nv_bfloat162* __restrict__ ol)
{
    size_t i = (size_t)blockIdx.x * 256 + threadIdx.x;
    float4 v = in[i];
    __nv_bfloat162 h0 = __floats2bfloat162_rn(v.x, v.y);
    __nv_bfloat162 h1 = __floats2bfloat162_rn(v.z, v.w);
    __nv_bfloat162 l0 = __floats2bfloat162_rn(v.x - __bfloat162float(h0.x),
                                              v.y - __bfloat162float(h0.y));
    __nv_bfloat162 l1 = __floats2bfloat162_rn(v.z - __bfloat162float(h1.x),
                                              v.w - __bfloat162float(h1.y));
    oh[2 * i] = h0; oh[2 * i + 1] = h1;
    ol[2 * i] = l0; ol[2 * i + 1] = l1;
}

// ---------------- merged W transpose + split: 3 weights in one launch ----------
__global__ __launch_bounds__(256)
void transpose_split_w(const float* __restrict__ W0, const float* __restrict__ W1,
                       const float* __restrict__ W2, bf16* __restrict__ oh,
                       bf16* __restrict__ ol)
{
    __shared__ float t[32][33];
    const float* in = (blockIdx.z == 0) ? W0 : (blockIdx.z == 1) ? W1 : W2;
    oh += (size_t)blockIdx.z * WSZ;
    ol += (size_t)blockIdx.z * WSZ;
    const int r0 = blockIdx.y * 32, c0 = blockIdx.x * 32;
    const int tx = threadIdx.x & 31, ty = threadIdx.x >> 5;
#pragma unroll
    for (int d = 0; d < 32; d += 8)
        t[ty + d][tx] = in[(size_t)(r0 + ty + d) * DM + c0 + tx];
    __syncthreads();
#pragma unroll
    for (int d = 0; d < 32; d += 8) {
        float v = t[tx][ty + d];
        bf16 h = __float2bfloat16(v);
        bf16 l = __float2bfloat16(v - __bfloat162float(h));
        size_t o = (size_t)(c0 + ty + d) * DM + r0 + tx;
        oh[o] = h; ol[o] = l;
    }
}

// ---------------- transpose + split: out[c][r] = in[r][c] (V^T) --------------
__global__ __launch_bounds__(256)
void transpose_split(const float* __restrict__ in, bf16* __restrict__ oh,
                     bf16* __restrict__ ol, int R, int C, size_t sI, size_t sO)
{
    __shared__ float t[32][33];
    in += (size_t)blockIdx.z * sI;
    oh += (size_t)blockIdx.z * sO;
    ol += (size_t)blockIdx.z * sO;
    const int r0 = blockIdx.y * 32, c0 = blockIdx.x * 32;
    const int tx = threadIdx.x & 31, ty = threadIdx.x >> 5;
#pragma unroll
    for (int d = 0; d < 32; d += 8)
        t[ty + d][tx] = in[(size_t)(r0 + ty + d) * C + c0 + tx];
    __syncthreads();
#pragma unroll
    for (int d = 0; d < 32; d += 8) {
        float v = t[tx][ty + d];
        bf16 h = __float2bfloat16(v);
        bf16 l = __float2bfloat16(v - __bfloat162float(h));
        size_t o = (size_t)(c0 + ty + d) * R + r0 + tx;
        oh[o] = h; ol[o] = l;
    }
}

// ---------------- causal softmax: fp32 scores -> hi/lo bf16 probs ----------------
// Warp-shuffle reductions: 2 barriers per block.
__global__ __launch_bounds__(256)
void softmax_split(const float* __restrict__ S, bf16* __restrict__ Sh, bf16* __restrict__ Sl)
{
    const int row = blockIdx.x, b = blockIdx.y;
    const size_t base = ((size_t)b * CTX + row) * CTX;
    const float* s = S + base;
    bf16* oh = Sh + base;
    bf16* ol = Sl + base;
    const int len = row + 1;
    const int rowEnd = ((row >> 7) + 1) << 7;    // PV never reads past this
    const int tid  = threadIdx.x;
    const int lane = tid & 31;
    const int wrp  = tid >> 5;

    __shared__ float buf[CTX];
    __shared__ float wred[8];
    const float scale = 0.03125f;   // 1/sqrt(1024)

    float lmax = -3.4e38f;
    for (int j = tid; j < len; j += 256) {
        float v = s[j] * scale;
        buf[j] = v;
        lmax = fmaxf(lmax, v);
    }
#pragma unroll
    for (int off = 16; off > 0; off >>= 1)
        lmax = fmaxf(lmax, __shfl_xor_sync(0xffffffffu, lmax, off));
    if (lane == 0) wred[wrp] = lmax;
    __syncthreads();
    float m = wred[0];
#pragma unroll
    for (int k = 1; k < 8; k++) m = fmaxf(m, wred[k]);

    float lsum = 0.0f;
    for (int j = tid; j < len; j += 256) {
        float e = __expf(buf[j] - m);
        buf[j] = e;
        lsum += e;
    }
#pragma unroll
    for (int off = 16; off > 0; off >>= 1)
        lsum += __shfl_xor_sync(0xffffffffu, lsum, off);
    __syncthreads();                 // wred reuse: all reads of round-1 done
    if (lane == 0) wred[wrp] = lsum;
    __syncthreads();
    float tot = wred[0];
#pragma unroll
    for (int k = 1; k < 8; k++) tot += wred[k];
    const float inv = 1.0f / tot;

    const bf16 z = __ushort_as_bfloat16(0);
    for (int j = tid; j < len; j += 256) {
        float p = buf[j] * inv;
        bf16 h = __float2bfloat16(p);
        oh[j] = h;
        ol[j] = __float2bfloat16(p - __bfloat162float(h));
    }
    for (int j = len + tid; j < rowEnd; j += 256) { oh[j] = z; ol[j] = z; }
}

// ---------------- launch ----------------
extern "C" void kernel_launch(void* const* d_in, const int* in_sizes, int n_in,
                              void* d_out, int out_size)
{
    const float* x  = (const float*)d_in[0];
    const float* Wq = (const float*)d_in[1];
    const float* Wk = (const float*)d_in[2];
    const float* Wv = (const float*)d_in[3];
    float* out = (float*)d_out;

    bf16 *xh, *xl, *wth, *wtl, *qh, *ql, *kh, *kl, *vth, *vtl, *sh, *sl;
    float *vf, *s;
    cudaGetSymbolAddress((void**)&xh, g_xh);   cudaGetSymbolAddress((void**)&xl, g_xl);
    cudaGetSymbolAddress((void**)&wth, g_wth); cudaGetSymbolAddress((void**)&wtl, g_wtl);
    cudaGetSymbolAddress((void**)&qh, g_qh);   cudaGetSymbolAddress((void**)&ql, g_ql);
    cudaGetSymbolAddress((void**)&kh, g_kh);   cudaGetSymbolAddress((void**)&kl, g_kl);
    cudaGetSymbolAddress((void**)&vf, g_vf);
    cudaGetSymbolAddress((void**)&vth, g_vth); cudaGetSymbolAddress((void**)&vtl, g_vtl);
    cudaGetSymbolAddress((void**)&s, g_s);
    cudaGetSymbolAddress((void**)&sh, g_sh);   cudaGetSymbolAddress((void**)&sl, g_sl);

    cudaFuncSetAttribute(gemm_bf16x3<2, false, false>,
                         cudaFuncAttributeMaxDynamicSharedMemorySize, GEMM_SMEM);
    cudaFuncSetAttribute(gemm_bf16x3<0, true, false>,
                         cudaFuncAttributeMaxDynamicSharedMemorySize, GEMM_SMEM);
    cudaFuncSetAttribute(gemm_bf16x3<0, false, true>,
                         cudaFuncAttributeMaxDynamicSharedMemorySize, GEMM_SMEM);

    // 1) split x into hi/lo bf16
    split_x<<<(unsigned)(XSZ / 4 / 256), 256>>>((const float4*)x,
                                                (__nv_bfloat162*)xh, (__nv_bfloat162*)xl);

    // 2) transpose + split weights (single z-indexed launch, Q,K,V contiguous)
    transpose_split_w<<<dim3(32, 32, 3), 256>>>(Wq, Wk, Wv, wth, wtl);

    // 3) fused QKV projection: [8192,3072] = x @ [Wq|Wk|Wv]^T
    gemm_bf16x3<2, false, false><<<dim3(24, 64, 1), 256, GEMM_SMEM>>>(
        xh, xl, wth, wtl, vf, qh, ql, kh, kl, (int)NTOK, 3 * DM, DM, 0, 0, 0);

    // 4) V^T per batch: [t][e] -> [e][t], split
    transpose_split<<<dim3(DM / 32, CTX / 32, BATCH), 256>>>(
        vf, vth, vtl, CTX, DM, (size_t)CTX * DM, (size_t)DM * CTX);

    // 5) scores = Q @ K^T — compact triangular grid (136 live tiles/batch)
    gemm_bf16x3<0, true, false><<<dim3(136, 1, BATCH), 256, GEMM_SMEM>>>(
        qh, ql, kh, kl, s, nullptr, nullptr, nullptr, nullptr, CTX, CTX, DM,
        (size_t)CTX * DM, (size_t)CTX * DM, (size_t)CTX * CTX);

    // 6) causal softmax -> hi/lo split probabilities (zeros only to 128-aligned end)
    softmax_split<<<dim3(CTX, BATCH), 256>>>(s, sh, sl);

    // 7) out = P @ V (causal K truncation, longest tiles first), per batch
    gemm_bf16x3<0, false, true><<<dim3(DM / 128, CTX / 128, BATCH), 256, GEMM_SMEM>>>(
        sh, sl, vth, vtl, out, nullptr, nullptr, nullptr, nullptr, CTX, DM, CTX,
        (size_t)CTX * CTX, (size_t)DM * CTX, (size_t)CTX * DM);
}